// round 8
// baseline (speedup 1.0000x reference)
#include <cuda_runtime.h>
#include <cuda_fp16.h>
#include <math.h>

#define B     64
#define P     196
#define D     2048
#define A_DIM 512
#define H     512
#define E     512
#define V     10000
#define VPAD  10048
#define T     19
#define LCAP  20
#define XH    3072
#define G4    2048
#define NSMALL 2560
#define GP_SLOTS 10    /* 0:emb 1:h 2..9: awe split-8 */
#define STAGES 3

// ---------------- device scratch ---------------------------------------------
__device__ __half g_featsh[(size_t)B*P*D];
__device__ __half g_att1h[(size_t)B*P*A_DIM];
__device__ __half g_Wcath[(size_t)G4*XH];
__device__ __half g_clswh[(size_t)VPAD*H];
__device__ __half g_encwh[(size_t)A_DIM*D];
__device__ __half g_smallw[(size_t)NSMALL*H];
__device__ __half g_hcwh[(size_t)2*H*D];
__device__ __half g_meanfh[B*D];
__device__ __half g_embh[(size_t)B*T*E];
__device__ __half g_xhh[(size_t)B*XH];
__device__ float  g_small_out[(size_t)B*NSMALL];
__device__ float  g_smallb[NSMALL];
__device__ float  g_hcb[2*H];
__device__ float  g_bcat[G4];
__device__ float  g_h0[B*H];
__device__ float  g_c[B*H];
__device__ float  g_gparts[(size_t)GP_SLOTS*B*G4];
__device__ unsigned g_bar;

__device__ __forceinline__ void st_half4(__half* dst, float4 v)
{
    ((__half2*)dst)[0] = __floats2half2_rn(v.x, v.y);
    ((__half2*)dst)[1] = __floats2half2_rn(v.z, v.w);
}

// ---------------- cp.async helpers --------------------------------------------
__device__ __forceinline__ void cp16(void* smem, const void* gmem)
{
    unsigned sa = (unsigned)__cvta_generic_to_shared(smem);
    asm volatile("cp.async.cg.shared.global [%0], [%1], 16;\n" :: "r"(sa), "l"(gmem));
}
#define CP_COMMIT() asm volatile("cp.async.commit_group;\n" ::: "memory")
#define CP_WAIT1()  asm volatile("cp.async.wait_group 1;\n" ::: "memory")
#define CP_WAIT0()  asm volatile("cp.async.wait_group 0;\n" ::: "memory")

// ---------------- preproc mega-kernel (elementwise, region dispatch) ----------
#define R0 131072
#define R1 262144
#define R2 1572864
#define R3 1286144
#define R4 327680
#define R5 524288
#define R6 155648
#define R7 2560
#define N_ELEM (R0+R1+R2+R3+R4+R5+R6+R7)

__global__ void k_prep_elem(
    const float* __restrict__ f,     const float* __restrict__ enc_w,
    const float* __restrict__ W_ih,  const float* __restrict__ b_ih,
    const float* __restrict__ W_hh,  const float* __restrict__ b_hh,
    const float* __restrict__ cls_w,
    const float* __restrict__ dec_w, const float* __restrict__ dec_b,
    const float* __restrict__ fb_w,  const float* __restrict__ fb_b,
    const float* __restrict__ h_fc_w,const float* __restrict__ h_fc_b,
    const float* __restrict__ c_fc_w,const float* __restrict__ c_fc_b,
    const float* __restrict__ emb,   const int* __restrict__ captions)
{
    int idx = blockIdx.x * 256 + threadIdx.x;

    if (idx < R0) {
        int b = idx >> 11, d = idx & (D-1);
        const float* p = f + (size_t)b*P*D + d;
        __half* o = g_featsh + (size_t)b*P*D + d;
        float s = 0.f;
        #pragma unroll 4
        for (int q = 0; q < P; q++) {
            float v = p[(size_t)q*D];
            s += v;
            o[(size_t)q*D] = __float2half(v);
        }
        g_meanfh[idx] = __float2half(s * (1.f/196.f));
        return;
    }
    idx -= R0;
    if (idx < R1) {
        size_t i = (size_t)idx * 4;
        st_half4(g_encwh + i, *(const float4*)(enc_w + i));
        return;
    }
    idx -= R1;
    if (idx < R2) {
        int j = idx / (XH/4);
        int k = (idx % (XH/4)) * 4;
        float4 v = (k < E + D) ? *(const float4*)(W_ih + (size_t)j*(E+D) + k)
                               : *(const float4*)(W_hh + (size_t)j*H + (k - (E+D)));
        st_half4(g_Wcath + (size_t)j*XH + k, v);
        return;
    }
    idx -= R2;
    if (idx < R3) {
        int n = idx >> 7, k = (idx & 127) * 4;
        float4 v = make_float4(0.f,0.f,0.f,0.f);
        if (n < V) v = *(const float4*)(cls_w + (size_t)n*H + k);
        st_half4(g_clswh + (size_t)n*H + k, v);
        return;
    }
    idx -= R3;
    if (idx < R4) {
        int n = idx >> 7, k = (idx & 127) * 4;
        const float* src = (n < A_DIM) ? dec_w + (size_t)n*H : fb_w + (size_t)(n - A_DIM)*H;
        st_half4(g_smallw + (size_t)n*H + k, *(const float4*)(src + k));
        return;
    }
    idx -= R4;
    if (idx < R5) {
        int n = idx >> 9, k = (idx & 511) * 4;
        const float* src = (n < H) ? h_fc_w + (size_t)n*D : c_fc_w + (size_t)(n - H)*D;
        st_half4(g_hcwh + (size_t)n*D + k, *(const float4*)(src + k));
        return;
    }
    idx -= R5;
    if (idx < R6) {
        int row = idx >> 7, e4 = (idx & 127) * 4;
        int b = row / T, t = row % T;
        int tok = captions[b*LCAP + t];
        st_half4(g_embh + (size_t)row*E + e4, *(const float4*)(emb + (size_t)tok*E + e4));
        return;
    }
    idx -= R6;
    if (idx < R7) {
        if (idx == 0) g_bar = 0u;
        if (idx < G4)  g_bcat[idx]   = b_ih[idx] + b_hh[idx];
        g_smallb[idx] = (idx < A_DIM) ? dec_b[idx] : fb_b[idx - A_DIM];
        if (idx < 2*H) g_hcb[idx]    = (idx < H) ? h_fc_b[idx] : c_fc_b[idx - H];
    }
}

// ---------------- HMMA cores ----------------------------------------------------
__device__ __forceinline__ void mma16816(float c[4], const unsigned a[4], const unsigned b[2])
{
    asm volatile(
        "mma.sync.aligned.m16n8k16.row.col.f32.f16.f16.f32 "
        "{%0,%1,%2,%3}, {%4,%5,%6,%7}, {%8,%9}, {%0,%1,%2,%3};"
        : "+f"(c[0]), "+f"(c[1]), "+f"(c[2]), "+f"(c[3])
        : "r"(a[0]), "r"(a[1]), "r"(a[2]), "r"(a[3]), "r"(b[0]), "r"(b[1]));
}

struct SmemP { __half As[STAGES][64][40]; __half Ws[STAGES][64][40]; };

// 64x64 tile, 3-stage cp.async pipeline
__device__ __forceinline__ void hmma_tile(
    const __half* __restrict__ Aptr, int ldA,
    const __half* __restrict__ Wptr, int ldW,
    SmemP* sm, float acc[2][2][4], int K)
{
    const int tid  = threadIdx.x;
    const int lane = tid & 31;
    const int wid  = tid >> 5;
    const int wm   = wid >> 2;
    const int wn   = wid & 3;
    const int grp  = lane >> 2;
    const int qp   = lane & 3;
    const int lrow = tid >> 2;
    const int lcol = (tid & 3) * 8;

    const __half* ap = Aptr + (size_t)lrow*ldA + lcol;
    const __half* wp = Wptr + (size_t)lrow*ldW + lcol;
    const int nch = K >> 5;

    __syncthreads();

    #pragma unroll
    for (int s = 0; s < STAGES-1; s++) {
        cp16(&sm->As[s][lrow][lcol], ap + s*32);
        cp16(&sm->Ws[s][lrow][lcol], wp + s*32);
        CP_COMMIT();
    }

    for (int c = 0; c < nch; c++) {
        const int st = c % STAGES;
        CP_WAIT1();
        __syncthreads();

        #pragma unroll
        for (int ks = 0; ks < 2; ks++) {
            const int kb = 16*ks + 2*qp;
            unsigned afr[2][4], bfr[2][2];
            #pragma unroll
            for (int mf = 0; mf < 2; mf++) {
                const int r = 32*wm + 16*mf + grp;
                afr[mf][0] = *(const unsigned*)&sm->As[st][r    ][kb    ];
                afr[mf][1] = *(const unsigned*)&sm->As[st][r + 8][kb    ];
                afr[mf][2] = *(const unsigned*)&sm->As[st][r    ][kb + 8];
                afr[mf][3] = *(const unsigned*)&sm->As[st][r + 8][kb + 8];
            }
            #pragma unroll
            for (int nf = 0; nf < 2; nf++) {
                const int r = 16*wn + 8*nf + grp;
                bfr[nf][0] = *(const unsigned*)&sm->Ws[st][r][kb    ];
                bfr[nf][1] = *(const unsigned*)&sm->Ws[st][r][kb + 8];
            }
            #pragma unroll
            for (int mf = 0; mf < 2; mf++)
                #pragma unroll
                for (int nf = 0; nf < 2; nf++)
                    mma16816(acc[mf][nf], afr[mf], bfr[nf]);
        }

        const int nc = c + STAGES - 1;
        if (nc < nch) {
            const int st2 = nc % STAGES;
            cp16(&sm->As[st2][lrow][lcol], ap + nc*32);
            cp16(&sm->Ws[st2][lrow][lcol], wp + nc*32);
        }
        CP_COMMIT();
    }
}

// ---------------- att1: 128x128 tiles, 2-stage cp.async -------------------------
struct Smem128 { __half A[2][128][40]; __half W[2][128][40]; };

__global__ void __launch_bounds__(256, 2) k_att1_128(const float* __restrict__ enc_b)
{
    __shared__ Smem128 sm;
    const int tid  = threadIdx.x;
    const int lane = tid & 31;
    const int wid  = tid >> 5;
    const int wm = wid >> 2;          // 0..1 (64 m-rows each)
    const int wn = wid & 3;           // 0..3 (32 n-cols each)
    const int grp = lane >> 2, qp = lane & 3;
    const int m0 = blockIdx.x * 128;
    const int n0 = blockIdx.y * 128;

    const int lrow = tid >> 1;            // 0..127
    const int lcol = (tid & 1) * 16;      // 0 or 16

    const __half* ap = g_featsh + (size_t)(m0 + lrow)*D + lcol;
    const __half* wp = g_encwh  + (size_t)(n0 + lrow)*D + lcol;

    float acc[4][4][4] = {};
    const int nch = D / 32;   // 64

    // prologue: load chunk 0 into stage 0
    cp16(&sm.A[0][lrow][lcol],     ap);
    cp16(&sm.A[0][lrow][lcol + 8], ap + 8);
    cp16(&sm.W[0][lrow][lcol],     wp);
    cp16(&sm.W[0][lrow][lcol + 8], wp + 8);
    CP_COMMIT();

    for (int c = 0; c < nch; c++) {
        const int st = c & 1;
        if (c + 1 < nch) {
            const int s2 = (c + 1) & 1;
            const __half* a2 = ap + (c + 1)*32;
            const __half* w2 = wp + (c + 1)*32;
            cp16(&sm.A[s2][lrow][lcol],     a2);
            cp16(&sm.A[s2][lrow][lcol + 8], a2 + 8);
            cp16(&sm.W[s2][lrow][lcol],     w2);
            cp16(&sm.W[s2][lrow][lcol + 8], w2 + 8);
            CP_COMMIT();
            CP_WAIT1();
        } else {
            CP_WAIT0();
        }
        __syncthreads();

        #pragma unroll
        for (int ks = 0; ks < 2; ks++) {
            const int kb = 16*ks + 2*qp;
            unsigned afr[4][4], bfr[4][2];
            #pragma unroll
            for (int mf = 0; mf < 4; mf++) {
                const int r = 64*wm + 16*mf + grp;
                afr[mf][0] = *(const unsigned*)&sm.A[st][r    ][kb    ];
                afr[mf][1] = *(const unsigned*)&sm.A[st][r + 8][kb    ];
                afr[mf][2] = *(const unsigned*)&sm.A[st][r    ][kb + 8];
                afr[mf][3] = *(const unsigned*)&sm.A[st][r + 8][kb + 8];
            }
            #pragma unroll
            for (int nf = 0; nf < 4; nf++) {
                const int r = 32*wn + 8*nf + grp;
                bfr[nf][0] = *(const unsigned*)&sm.W[st][r][kb    ];
                bfr[nf][1] = *(const unsigned*)&sm.W[st][r][kb + 8];
            }
            #pragma unroll
            for (int mf = 0; mf < 4; mf++)
                #pragma unroll
                for (int nf = 0; nf < 4; nf++)
                    mma16816(acc[mf][nf], afr[mf], bfr[nf]);
        }
        __syncthreads();    // stage st reused in iteration c+2
    }

    #pragma unroll
    for (int mf = 0; mf < 4; mf++)
        #pragma unroll
        for (int nf = 0; nf < 4; nf++)
            #pragma unroll
            for (int q = 0; q < 4; q++) {
                int m = m0 + 64*wm + 16*mf + grp + (q >> 1)*8;
                int n = n0 + 32*wn + 8*nf + 2*qp + (q & 1);
                g_att1h[(size_t)m*A_DIM + n] = __float2half(acc[mf][nf][q] + enc_b[n]);
            }
}

// ---------------- h0/c0 GEMM (16 tiles, 64x64 path) -----------------------------
__global__ void __launch_bounds__(256, 2) k_prep_hc()
{
    __shared__ SmemP sm;
    const int tid  = threadIdx.x;
    const int lane = tid & 31;
    const int wid  = tid >> 5;
    const int wm = wid >> 2, wn = wid & 3, grp = lane >> 2, qp = lane & 3;
    const int n0 = blockIdx.x * 64;
    float acc[2][2][4] = {};
    hmma_tile(g_meanfh, D, g_hcwh + (size_t)n0*D, D, &sm, acc, D);
    #pragma unroll
    for (int mf = 0; mf < 2; mf++)
        #pragma unroll
        for (int nf = 0; nf < 2; nf++)
            #pragma unroll
            for (int q = 0; q < 4; q++) {
                int m = 32*wm + 16*mf + grp + (q >> 1)*8;
                int n = n0 + 16*wn + 8*nf + 2*qp + (q & 1);
                float v = acc[mf][nf][q] + g_hcb[n];
                if (n < H) g_h0[(size_t)m*H + n] = v;
                else       g_c [(size_t)m*H + n - H] = v;
            }
}

// ---------------- grid barrier ---------------------------------------------------
__device__ __forceinline__ void gbar(int nblk, int& target)
{
    __syncthreads();
    target += nblk;
    if (threadIdx.x == 0) {
        __threadfence();
        atomicAdd(&g_bar, 1u);
        while (__ldcg(&g_bar) < (unsigned)target)
            __nanosleep(64);
        __threadfence();
    }
    __syncthreads();
}

// ---------------- persistent decode --------------------------------------------
__global__ void __launch_bounds__(256, 2) k_decode(
    const int*   __restrict__ lengths,
    const float* __restrict__ attw,
    const float* __restrict__ attb,
    const float* __restrict__ cls_b,
    float* __restrict__ outy,
    float* __restrict__ outa)
{
    __shared__ SmemP sm;
    __shared__ float sred[256];
    __shared__ float sal[256];
    const int nblk = gridDim.x;
    const int bid  = blockIdx.x;
    const int tid  = threadIdx.x;
    const int lane = tid & 31;
    const int wid  = tid >> 5;
    const int wm = wid >> 2, wn = wid & 3, grp = lane >> 2, qp = lane & 3;
    int target = 0;

    // ---- init: xhh = [emb(t=0) | - | h0]
    for (int i = bid*256 + tid; i < B*H; i += nblk*256) {
        const int b = i >> 9, j = i & (H-1);
        g_xhh[(size_t)b*XH + j]         = g_embh[(size_t)(b*T)*E + j];
        g_xhh[(size_t)b*XH + E + D + j] = __float2half(g_h0[i]);
    }
    gbar(nblk, target);

    for (int t = 0; t < T; t++) {
        // ==== Phase A: small (0..39) + gates emb|h (40..103) + cls(t-1) (104..260)
        const int ntA = (t > 0) ? 261 : 104;
        for (int tile = bid; tile < ntA; tile += nblk) {
            float acc[2][2][4] = {};
            if (tile < 40) {
                const int n0 = tile * 64;
                hmma_tile(g_xhh + (E + D), XH, g_smallw + (size_t)n0*H, H, &sm, acc, H);
                #pragma unroll
                for (int mf = 0; mf < 2; mf++)
                    #pragma unroll
                    for (int nf = 0; nf < 2; nf++)
                        #pragma unroll
                        for (int q = 0; q < 4; q++) {
                            int m = 32*wm + 16*mf + grp + (q >> 1)*8;
                            int n = n0 + 16*wn + 8*nf + 2*qp + (q & 1);
                            float v = acc[mf][nf][q] + g_smallb[n];
                            if (n >= A_DIM) v = 1.f / (1.f + expf(-v));
                            g_small_out[(size_t)m*NSMALL + n] = v;
                        }
            } else if (tile < 104) {
                const int it = tile - 40;
                const int n0 = (it & 31) * 64;
                const int part = it >> 5;
                const int koff = part ? (E + D) : 0;
                hmma_tile(g_xhh + koff, XH, g_Wcath + (size_t)n0*XH + koff, XH, &sm, acc, H);
                #pragma unroll
                for (int mf = 0; mf < 2; mf++)
                    #pragma unroll
                    for (int nf = 0; nf < 2; nf++)
                        #pragma unroll
                        for (int q = 0; q < 4; q++) {
                            int m = 32*wm + 16*mf + grp + (q >> 1)*8;
                            int n = n0 + 16*wn + 8*nf + 2*qp + (q & 1);
                            g_gparts[(size_t)part*B*G4 + (size_t)m*G4 + n] = acc[mf][nf][q];
                        }
            } else {
                const int n0 = (tile - 104) * 64;
                hmma_tile(g_xhh + (E + D), XH, g_clswh + (size_t)n0*H, H, &sm, acc, H);
                const int tp = t - 1;
                #pragma unroll
                for (int mf = 0; mf < 2; mf++)
                    #pragma unroll
                    for (int nf = 0; nf < 2; nf++)
                        #pragma unroll
                        for (int q = 0; q < 4; q++) {
                            int m = 32*wm + 16*mf + grp + (q >> 1)*8;
                            int n = n0 + 16*wn + 8*nf + 2*qp + (q & 1);
                            if (n < V) {
                                int act = tp < (lengths[m] - 1);
                                outy[(size_t)m*T*V + (size_t)tp*V + n] =
                                    act ? (acc[mf][nf][q] + cls_b[n]) : 0.f;
                            }
                        }
            }
        }
        gbar(nblk, target);

        // ==== Phase B (fused): e -> softmax -> awe; block = (b, quarter)
        for (int bq = bid; bq < B*4; bq += nblk) {
            const int b = bq >> 2, qtr = bq & 3;
            const float* a2f = g_small_out + (size_t)b * NSMALL;

            // e scores (all 196, redundantly per quarter-block)
            for (int p = wid; p < P; p += 8) {
                const __half2* a1 = (const __half2*)(g_att1h + (size_t)(b*P + p) * A_DIM);
                const float2*  a2 = (const float2*)a2f;
                const float2*  aw = (const float2*)attw;
                float s = 0.f;
                #pragma unroll
                for (int a = lane; a < A_DIM/2; a += 32) {
                    float2 v1 = __half22float2(a1[a]);
                    float2 v2 = a2[a];
                    float2 w2 = aw[a];
                    float x = v1.x + v2.x, y = v1.y + v2.y;
                    if (x > 0.f) s += x * w2.x;
                    if (y > 0.f) s += y * w2.y;
                }
                #pragma unroll
                for (int o = 16; o; o >>= 1) s += __shfl_xor_sync(0xffffffffu, s, o);
                if (lane == 0) sal[p] = s + attb[0];
            }
            __syncthreads();

            // softmax over sal[0..195]
            float ev = (tid < P) ? sal[tid] : -1e30f;
            sred[tid] = ev; __syncthreads();
            for (int s2 = 128; s2 > 0; s2 >>= 1) {
                if (tid < s2) sred[tid] = fmaxf(sred[tid], sred[tid + s2]);
                __syncthreads();
            }
            float mx = sred[0]; __syncthreads();
            float ex = (tid < P) ? expf(ev - mx) : 0.f;
            sred[tid] = ex; __syncthreads();
            for (int s2 = 128; s2 > 0; s2 >>= 1) {
                if (tid < s2) sred[tid] += sred[tid + s2];
                __syncthreads();
            }
            float inv = 1.f / sred[0];
            __syncthreads();
            if (tid < P) sal[tid] = ex * inv;
            __syncthreads();

            // awe for this quarter (512 floats = 256 half2), deep MLP
            const __half2* fb = (const __half2*)g_featsh + (size_t)b*P*(D/2) + qtr*256 + tid;
            float2 s0 = {0.f,0.f}, s1 = {0.f,0.f}, s2v = {0.f,0.f}, s3 = {0.f,0.f};
            #pragma unroll 4
            for (int p = 0; p < 196; p += 4) {
                float2 f0 = __half22float2(fb[(size_t)(p+0)*(D/2)]);
                float2 f1 = __half22float2(fb[(size_t)(p+1)*(D/2)]);
                float2 f2 = __half22float2(fb[(size_t)(p+2)*(D/2)]);
                float2 f3 = __half22float2(fb[(size_t)(p+3)*(D/2)]);
                s0.x += sal[p+0]*f0.x; s0.y += sal[p+0]*f0.y;
                s1.x += sal[p+1]*f1.x; s1.y += sal[p+1]*f1.y;
                s2v.x += sal[p+2]*f2.x; s2v.y += sal[p+2]*f2.y;
                s3.x += sal[p+3]*f3.x; s3.y += sal[p+3]*f3.y;
            }
            float2 acc2 = make_float2((s0.x+s1.x)+(s2v.x+s3.x), (s0.y+s1.y)+(s2v.y+s3.y));
            const int d = qtr*512 + 2*tid;
            acc2.x *= a2f[A_DIM + d];
            acc2.y *= a2f[A_DIM + d + 1];
            *(__half2*)&g_xhh[(size_t)b*XH + E + d] = __floats2half2_rn(acc2.x, acc2.y);

            if (qtr == 0 && tid < P) {
                int act = t < (lengths[b] - 1);
                outa[((size_t)b*T + t)*P + tid] = act ? sal[tid] : 0.f;
            }
            __syncthreads();
        }
        gbar(nblk, target);

        // ==== Phase C: gates awe-part, 32 n-tiles x split-8 over K=2048
        for (int tile = bid; tile < 256; tile += nblk) {
            const int n0 = (tile & 31) * 64;
            const int ks = tile >> 5;
            const int koff = E + ks*256;
            float acc[2][2][4] = {};
            hmma_tile(g_xhh + koff, XH, g_Wcath + (size_t)n0*XH + koff, XH, &sm, acc, 256);
            #pragma unroll
            for (int mf = 0; mf < 2; mf++)
                #pragma unroll
                for (int nf = 0; nf < 2; nf++)
                    #pragma unroll
                    for (int q = 0; q < 4; q++) {
                        int m = 32*wm + 16*mf + grp + (q >> 1)*8;
                        int n = n0 + 16*wn + 8*nf + 2*qp + (q & 1);
                        g_gparts[(size_t)(2 + ks)*B*G4 + (size_t)m*G4 + n] = acc[mf][nf][q];
                    }
        }
        gbar(nblk, target);

        // ==== Phase D: LSTM pointwise + stage next emb
        for (int i = bid*256 + tid; i < B*H; i += nblk*256) {
            const int b = i >> 9, j = i & (H-1);
            float gi = g_bcat[j], gf = g_bcat[j + H], gg = g_bcat[j + 2*H], go = g_bcat[j + 3*H];
            #pragma unroll
            for (int s = 0; s < GP_SLOTS; s++) {
                const float* pp = g_gparts + (size_t)s*B*G4 + (size_t)b*G4;
                gi += pp[j]; gf += pp[j + H]; gg += pp[j + 2*H]; go += pp[j + 3*H];
            }
            float si = 1.f / (1.f + expf(-gi));
            float sf = 1.f / (1.f + expf(-gf));
            float so = 1.f / (1.f + expf(-go));
            float c2 = sf * g_c[i] + si * tanhf(gg);
            float h2 = so * tanhf(c2);
            g_c[i] = c2;
            g_xhh[(size_t)b*XH + E + D + j] = __float2half(h2);
            if (t + 1 < T) g_xhh[(size_t)b*XH + j] = g_embh[(size_t)(b*T + (t+1))*E + j];
        }
        gbar(nblk, target);
    }

    // ---- final cls (t = T-1)
    for (int tile = bid; tile < 157; tile += nblk) {
        const int n0 = tile * 64;
        float acc[2][2][4] = {};
        hmma_tile(g_xhh + (E + D), XH, g_clswh + (size_t)n0*H, H, &sm, acc, H);
        const int tp = T - 1;
        #pragma unroll
        for (int mf = 0; mf < 2; mf++)
            #pragma unroll
            for (int nf = 0; nf < 2; nf++)
                #pragma unroll
                for (int q = 0; q < 4; q++) {
                    int m = 32*wm + 16*mf + grp + (q >> 1)*8;
                    int n = n0 + 16*wn + 8*nf + 2*qp + (q & 1);
                    if (n < V) {
                        int act = tp < (lengths[m] - 1);
                        outy[(size_t)m*T*V + (size_t)tp*V + n] =
                            act ? (acc[mf][nf][q] + cls_b[n]) : 0.f;
                    }
                }
    }
}

// ---------------- host driver ---------------------------------------------------
extern "C" void kernel_launch(void* const* d_in, const int* in_sizes, int n_in,
                              void* d_out, int out_size)
{
    const float* features = (const float*)d_in[0];
    const int*   captions = (const int*)  d_in[1];
    const int*   lengths  = (const int*)  d_in[2];
    const float* emb      = (const float*)d_in[3];
    const float* W_ih     = (const float*)d_in[4];
    const float* b_ih     = (const float*)d_in[5];
    const float* W_hh     = (const float*)d_in[6];
    const float* b_hh     = (const float*)d_in[7];
    const float* h_fc_w   = (const float*)d_in[8];
    const float* h_fc_b   = (const float*)d_in[9];
    const float* c_fc_w   = (const float*)d_in[10];
    const float* c_fc_b   = (const float*)d_in[11];
    const float* f_beta_w = (const float*)d_in[12];
    const float* f_beta_b = (const float*)d_in[13];
    const float* cls_w    = (const float*)d_in[14];
    const float* cls_b    = (const float*)d_in[15];
    const float* enc_w    = (const float*)d_in[16];
    const float* enc_b    = (const float*)d_in[17];
    const float* dec_w    = (const float*)d_in[18];
    const float* dec_b    = (const float*)d_in[19];
    const float* att_w    = (const float*)d_in[20];
    const float* att_b    = (const float*)d_in[21];

    float* outy = (float*)d_out;
    float* outa = outy + (size_t)B*T*V;

    int nsm = 148;
    cudaDeviceGetAttribute(&nsm, cudaDevAttrMultiProcessorCount, 0);

    k_prep_elem<<<N_ELEM/256, 256>>>(features, enc_w, W_ih, b_ih, W_hh, b_hh, cls_w,
                                     dec_w, dec_b, f_beta_w, f_beta_b,
                                     h_fc_w, h_fc_b, c_fc_w, c_fc_b, emb, captions);
    k_att1_128 <<<dim3((B*P)/128, A_DIM/128), 256>>>(enc_b);
    k_prep_hc  <<<2*H/64, 256>>>();
    k_decode   <<<2*nsm, 256>>>(lengths, att_w, att_b, cls_b, outy, outa);
}